// round 12
// baseline (speedup 1.0000x reference)
#include <cuda_runtime.h>
#include <cuda_fp16.h>
#include <mma.h>
#include <cstdint>

using namespace nvcuda;

// Problem constants
#define B_WIN   4096
#define NTOK    49
#define CDIM    384
#define NHEADS  12
#define HDIM    32
#define NWIN    1024
#define SCALE_Q 0.17677669529663687f  // 32^-0.5

// Precomputed-weight globals (~1.5 MB)
__device__ __align__(256) __half g_wqkv[NHEADS * 96 * CDIM];  // head-permuted qkv_w
__device__ __align__(256) __half g_wpj_h[CDIM * CDIM];        // proj_w hi
__device__ __align__(256) __half g_wpj_l[CDIM * CDIM];        // proj_w lo

// Shared memory layout (byte offsets)
#define SM_XH   0        // Xh: 64 x 392 half = 50176
#define SM_WB   50176    // W staging 2 x 13824 halves = 55296 B; qkv aliases (30720 B)
#define SM_SCR  105472   // per-warp scratch: warps0-7: 4352 B, warps8-15: 1024 B = 43008
#define SM_OH   148480   // Oh: 64 x 392 half = 50176
#define SM_MS   198656   // mask f32: 49 x 50 = 9800 (+pad 9824)
#define SM_RB   208480   // rpb all heads fp16: 12 x 169 = 4056 (+pad 4064)
#define SM_PAR  212544   // qkv_b(1152)+proj_b(384)+lamb(12) f32 = 6192 (+pad 6208)
#define SMEM_BYTES 218752

#define XLD   392        // Xh/Oh ld (halves)
#define WLD   72         // W staging ld (halves)
#define WBUF  13824      // halves per W buffer (192*72)
#define KVLD  40         // qkv ld (halves)
#define SLD   68         // scratch S/O f32 ld
#define SHLD  72         // scratch Sh half ld
#define PLOFF 6912       // proj lo offset within a buffer (halves)
#define NT    512

// ---------------------------------------------------------------------------
__global__ void prep_qkv_w(const float* __restrict__ qkv_w)
{
    int idx = blockIdx.x * 256 + threadIdx.x;
    if (idx < NHEADS * 96 * CDIM) {
        int h   = idx / (96 * CDIM);
        int rem = idx % (96 * CDIM);
        int j   = rem / CDIM;
        int k   = rem % CDIM;
        int g   = (j >> 5) * CDIM + h * HDIM + (j & 31);
        g_wqkv[idx] = __float2half_rn(qkv_w[(size_t)g * CDIM + k]);
    }
}

__global__ void prep_proj_w(const float* __restrict__ proj_w)
{
    int idx = blockIdx.x * 256 + threadIdx.x;
    if (idx < CDIM * CDIM) {
        float v = proj_w[idx];
        __half hi = __float2half_rn(v);
        g_wpj_h[idx] = hi;
        g_wpj_l[idx] = __float2half_rn(v - __half2float(hi));
    }
}

// ---------------------------------------------------------------------------
// Fused window attention: one block per window, 512 threads, head-pair groups,
// register-staged double-buffered GEMM, fully warp-local attention + epilogues.
// ---------------------------------------------------------------------------
__global__ void __launch_bounds__(NT, 1)
winattn_kernel(const float* __restrict__ x,
               const float* __restrict__ mask,
               const float* __restrict__ qkv_b,
               const float* __restrict__ proj_b,
               const float* __restrict__ rpb,
               const float* __restrict__ lamb,
               float* __restrict__ out)
{
    extern __shared__ __align__(16) char smraw[];
    __half* Xh  = (__half*)(smraw + SM_XH);
    __half* WB  = (__half*)(smraw + SM_WB);
    __half* qkv = WB;                               // aliases WB (phase-disjoint)
    __half* Oh  = (__half*)(smraw + SM_OH);
    float*  ms  = (float*)(smraw + SM_MS);
    __half* rb  = (__half*)(smraw + SM_RB);
    float*  par = (float*)(smraw + SM_PAR);

    const int tid = threadIdx.x;
    const int wp  = tid >> 5;
    const int l   = tid & 31;
    const int w   = blockIdx.x;

    // per-warp scratch: warps 0-7 get 4352 B (S/Sh/O), warps 8-15 get 1024 B
    float* scrF = (wp < 8)
        ? (float*)(smraw + SM_SCR + wp * 4352)
        : (float*)(smraw + SM_SCR + 8 * 4352 + (wp - 8) * 1024);

    // GEMM staging map: 192x64-half chunk = 1536 int4, 3 per thread
    int sj[3], sk[3];
#pragma unroll
    for (int i = 0; i < 3; ++i) {
        int v = tid + i * NT;
        sj[i] = v >> 3;
        sk[i] = (v & 7) << 3;
    }
    // proj staging map: hi(768 int4) + lo(768 int4)
    int pj[3], pk[3], psel[3];
#pragma unroll
    for (int i = 0; i < 3; ++i) {
        int v = tid + i * NT;
        psel[i] = (v >= 768);
        int v2 = v - psel[i] * 768;
        pj[i] = v2 >> 3;
        pk[i] = (v2 & 7) << 3;
    }

    // ---- issue group-0 chunk-0 weight loads early ----
    int4 st[3];
#pragma unroll
    for (int i = 0; i < 3; ++i)
        st[i] = *(const int4*)(g_wqkv + (size_t)sj[i] * CDIM + sk[i]);

    // ---- init ----
    for (int t = tid; t < 49 * 96; t += NT) {
        int r = t / 96, c4 = (t % 96) * 4;
        float4 v = *(const float4*)&x[((size_t)w * NTOK + r) * CDIM + c4];
        *(__half2*)&Xh[r * XLD + c4]     = __floats2half2_rn(v.x, v.y);
        *(__half2*)&Xh[r * XLD + c4 + 2] = __floats2half2_rn(v.z, v.w);
    }
    for (int t = tid; t < 15 * 196; t += NT) {        // zero pad rows 49..63
        int r = 49 + t / 196, c2 = (t % 196) * 2;
        __half2 z = __floats2half2_rn(0.0f, 0.0f);
        *(__half2*)&Xh[r * XLD + c2] = z;
        *(__half2*)&Oh[r * XLD + c2] = z;
    }
    {
        const float* mrow = mask + (size_t)(w & (NWIN - 1)) * (NTOK * NTOK);
        for (int t = tid; t < NTOK * NTOK; t += NT)
            ms[(t / 49) * 50 + (t % 49)] = mrow[t];
    }
    for (int t = tid; t < NHEADS * 169; t += NT)
        rb[t] = __float2half_rn(rpb[(t % 169) * NHEADS + (t / 169)]);
    for (int t = tid; t < 1548; t += NT)
        par[t] = (t < 1152) ? qkv_b[t] : (t < 1536 ? proj_b[t - 1152] : lamb[t - 1536]);
    // stage chunk 0 -> buf0
#pragma unroll
    for (int i = 0; i < 3; ++i)
        *(int4*)(WB + sj[i] * WLD + sk[i]) = st[i];
    __syncthreads();

    const int mt = wp & 3;           // GEMM m-tile (16 rows)
    const int nb = (wp >> 2) * 48;   // QKV GEMM n-base (0,48,96,144)

    // softmax lane constants
    const int j0 = l, j1 = l + 32;
    const int j0d = j0 / 7, j0m = j0 % 7;
    const int j1d = j1 / 7, j1m = j1 % 7;

    // =============== 6 groups of 2 heads ===============
    for (int g = 0; g < 6; ++g) {
        const int h0 = 2 * g;
        const __half* Wg = g_wqkv + (size_t)h0 * (96 * CDIM);

        // ---- QKV GEMM: 64x192 = Xh @ Wg^T, Kc=64, register-staged dbl buffer ----
        wmma::fragment<wmma::accumulator, 16, 16, 16, float> acc[3];
#pragma unroll
        for (int j = 0; j < 3; ++j) wmma::fill_fragment(acc[j], 0.0f);

        for (int c = 0; c < 6; ++c) {
            if (c < 5) {
#pragma unroll
                for (int i = 0; i < 3; ++i)
                    st[i] = *(const int4*)(Wg + (size_t)sj[i] * CDIM + (c + 1) * 64 + sk[i]);
            } else if (g < 5) {
                const __half* Wn = Wg + 192 * CDIM;   // next group's weights
#pragma unroll
                for (int i = 0; i < 3; ++i)
                    st[i] = *(const int4*)(Wn + (size_t)sj[i] * CDIM + sk[i]);
            }
            const __half* Wc = WB + (c & 1) * WBUF;
#pragma unroll
            for (int ks = 0; ks < 4; ++ks) {
                wmma::fragment<wmma::matrix_a, 16, 16, 16, __half, wmma::row_major> a1;
                wmma::load_matrix_sync(a1, &Xh[mt * 16 * XLD + c * 64 + ks * 16], XLD);
#pragma unroll
                for (int j = 0; j < 3; ++j) {
                    wmma::fragment<wmma::matrix_b, 16, 16, 16, __half, wmma::col_major> b1;
                    wmma::load_matrix_sync(b1, &Wc[(nb + j * 16) * WLD + ks * 16], WLD);
                    wmma::mma_sync(acc[j], a1, b1, acc[j]);
                }
            }
            if (c < 5) {
#pragma unroll
                for (int i = 0; i < 3; ++i)
                    *(int4*)(WB + ((c + 1) & 1) * WBUF + sj[i] * WLD + sk[i]) = st[i];
            }
            __syncthreads();
        }

        // ---- per-warp epilogue: acc -> scratch -> qkv fp16 (bias + q-scale) ----
#pragma unroll
        for (int j = 0; j < 3; ++j) {
            wmma::store_matrix_sync(scrF, acc[j], 16, wmma::mem_row_major);
            __syncwarp();
#pragma unroll
            for (int e2 = 0; e2 < 8; ++e2) {
                int e = l + e2 * 32;
                int r = e >> 4, cc = e & 15;
                int row = mt * 16 + r;
                int col = nb + j * 16 + cc;                 // 0..191
                int hh = col / 96, c2 = col % 96, which = c2 >> 5, d = c2 & 31;
                float v = scrF[e] + par[which * CDIM + (h0 + hh) * HDIM + d];
                if (which == 0) v *= SCALE_Q;
                qkv[hh * 7680 + which * 2560 + row * KVLD + d] =
                    (row < NTOK) ? __float2half_rn(v) : __float2half_rn(0.0f);
            }
            __syncwarp();
        }
        __syncthreads();   // qkv ready for cross-warp reads

        // ---- warp-local attention: 8 strips (2 heads x 4 m-strips) ----
        if (wp < 8) {
            const int hh = wp >> 2, mi = wp & 3;
            const int h  = h0 + hh;
            const __half* qh = qkv + hh * 7680;
            const __half* kh = qh + 2560;
            const __half* vh = qh + 5120;
            __half* ShS = (__half*)scrF;

            // S strip: 16 x 64 into scratch f32 (ld SLD)
            wmma::fragment<wmma::matrix_a, 16, 16, 16, __half, wmma::row_major> aq[2];
            wmma::load_matrix_sync(aq[0], &qh[mi * 16 * KVLD], KVLD);
            wmma::load_matrix_sync(aq[1], &qh[mi * 16 * KVLD + 16], KVLD);
#pragma unroll
            for (int nj = 0; nj < 4; ++nj) {
                wmma::fragment<wmma::accumulator, 16, 16, 16, float> sacc;
                wmma::fill_fragment(sacc, 0.0f);
#pragma unroll
                for (int ks = 0; ks < 2; ++ks) {
                    wmma::fragment<wmma::matrix_b, 16, 16, 16, __half, wmma::col_major> b1;
                    wmma::load_matrix_sync(b1, &kh[nj * 16 * KVLD + ks * 16], KVLD);
                    wmma::mma_sync(sacc, aq[ks], b1, sacc);
                }
                wmma::store_matrix_sync(scrF + nj * 16, sacc, SLD, wmma::mem_row_major);
            }
            __syncwarp();

            // softmax 16 rows (warp-local; Sh fp16 aliases S scratch — safe ordering)
            const float lam1 = 1.0f + par[1536 + h];
            const float invn = 1.0f / (float)NTOK;
            const __half* rbh = rb + h * 169;
#pragma unroll
            for (int r = 0; r < 16; ++r) {
                const int i = mi * 16 + r;
                if (i < NTOK) {
                    const int i7 = i / 7, im = i - i7 * 7;
                    const int r0 = (i7 - j0d + 6) * 13 + (im - j0m + 6);
                    float s0 = scrF[r * SLD + j0] + __half2float(rbh[r0]) + ms[i * 50 + j0];
                    float s1 = -1e30f;
                    if (j1 < NTOK) {
                        const int r1 = (i7 - j1d + 6) * 13 + (im - j1m + 6);
                        s1 = scrF[r * SLD + j1] + __half2float(rbh[r1]) + ms[i * 50 + j1];
                    }
                    float mx = fmaxf(s0, s1);
#pragma unroll
                    for (int off = 16; off > 0; off >>= 1)
                        mx = fmaxf(mx, __shfl_xor_sync(0xffffffffu, mx, off));
                    float e0 = __expf(s0 - mx);
                    float e1 = (j1 < NTOK) ? __expf(s1 - mx) : 0.0f;
                    float sm = e0 + e1;
#pragma unroll
                    for (int off = 16; off > 0; off >>= 1)
                        sm += __shfl_xor_sync(0xffffffffu, sm, off);
                    const float inv = 1.0f / sm;
                    ShS[r * SHLD + j0] = __float2half_rn(invn + (e0 * inv - invn) * lam1);
                    ShS[r * SHLD + j1] = (j1 < NTOK)
                        ? __float2half_rn(invn + (e1 * inv - invn) * lam1)
                        : __float2half_rn(0.0f);
                } else {
                    ShS[r * SHLD + j0] = __float2half_rn(0.0f);
                    ShS[r * SHLD + j1] = __float2half_rn(0.0f);
                }
            }
            __syncwarp();

            // O strip: Sh(16x64) @ v(64x32) -> 2 tiles
            wmma::fragment<wmma::accumulator, 16, 16, 16, float> oacc[2];
            wmma::fill_fragment(oacc[0], 0.0f);
            wmma::fill_fragment(oacc[1], 0.0f);
#pragma unroll
            for (int ks = 0; ks < 4; ++ks) {
                wmma::fragment<wmma::matrix_a, 16, 16, 16, __half, wmma::row_major> a1;
                wmma::load_matrix_sync(a1, &ShS[ks * 16], SHLD);
#pragma unroll
                for (int nj = 0; nj < 2; ++nj) {
                    wmma::fragment<wmma::matrix_b, 16, 16, 16, __half, wmma::row_major> b1;
                    wmma::load_matrix_sync(b1, &vh[ks * 16 * KVLD + nj * 16], KVLD);
                    wmma::mma_sync(oacc[nj], a1, b1, oacc[nj]);
                }
            }
            wmma::store_matrix_sync(scrF,      oacc[0], SLD, wmma::mem_row_major);
            wmma::store_matrix_sync(scrF + 16, oacc[1], SLD, wmma::mem_row_major);
            __syncwarp();
#pragma unroll
            for (int e2 = 0; e2 < 16; ++e2) {
                int e = l + e2 * 32;          // 0..511
                int r = e >> 5, cc = e & 31;
                int i = mi * 16 + r;
                if (i < NTOK)
                    Oh[i * XLD + h * HDIM + cc] = __float2half_rn(scrF[r * SLD + cc]);
            }
        }
        __syncthreads();   // Oh written; qkv free

        // ---- stage next group's chunk 0 -> buf0 ----
        if (g < 5) {
#pragma unroll
            for (int i = 0; i < 3; ++i)
                *(int4*)(WB + sj[i] * WLD + sk[i]) = st[i];
            __syncthreads();
        }
    }

    // =============== proj: out = Oh @ proj_w^T + b (hi/lo staged) ===============
    const int pm  = wp & 3;
    const int pn0 = wp >> 2;        // 0..3
    const int pn1 = pn0 + 4;        // 4..5 valid when wp < 8

    int4 pst[3];
#pragma unroll
    for (int i = 0; i < 3; ++i)
        pst[i] = *(const int4*)((psel[i] ? g_wpj_l : g_wpj_h)
                                + (size_t)pj[i] * CDIM + pk[i]);
#pragma unroll
    for (int i = 0; i < 3; ++i)
        *(int4*)(WB + psel[i] * PLOFF + pj[i] * WLD + pk[i]) = pst[i];
    __syncthreads();

    for (int p = 0; p < 4; ++p) {
        wmma::fragment<wmma::accumulator, 16, 16, 16, float> accA, accB;
        wmma::fill_fragment(accA, 0.0f);
        wmma::fill_fragment(accB, 0.0f);

        for (int c = 0; c < 6; ++c) {
            const bool more = (c < 5) || (p < 3);
            if (more) {
                const int np_ = (c < 5) ? p : p + 1;
                const int nc_ = (c < 5) ? c + 1 : 0;
#pragma unroll
                for (int i = 0; i < 3; ++i)
                    pst[i] = *(const int4*)((psel[i] ? g_wpj_l : g_wpj_h)
                             + (size_t)(np_ * 96 + pj[i]) * CDIM + nc_ * 64 + pk[i]);
            }
            const __half* Wc = WB + (c & 1) * WBUF;
#pragma unroll
            for (int ks = 0; ks < 4; ++ks) {
                wmma::fragment<wmma::matrix_a, 16, 16, 16, __half, wmma::row_major> a1;
                wmma::load_matrix_sync(a1, &Oh[pm * 16 * XLD + c * 64 + ks * 16], XLD);
                wmma::fragment<wmma::matrix_b, 16, 16, 16, __half, wmma::col_major> bh, bl;
                wmma::load_matrix_sync(bh, &Wc[pn0 * 16 * WLD + ks * 16], WLD);
                wmma::load_matrix_sync(bl, &Wc[PLOFF + pn0 * 16 * WLD + ks * 16], WLD);
                wmma::mma_sync(accA, a1, bh, accA);
                wmma::mma_sync(accA, a1, bl, accA);
                if (wp < 8) {
                    wmma::load_matrix_sync(bh, &Wc[pn1 * 16 * WLD + ks * 16], WLD);
                    wmma::load_matrix_sync(bl, &Wc[PLOFF + pn1 * 16 * WLD + ks * 16], WLD);
                    wmma::mma_sync(accB, a1, bh, accB);
                    wmma::mma_sync(accB, a1, bl, accB);
                }
            }
            if (more) {
#pragma unroll
                for (int i = 0; i < 3; ++i)
                    *(int4*)(WB + ((c + 1) & 1) * WBUF
                             + psel[i] * PLOFF + pj[i] * WLD + pk[i]) = pst[i];
            }
            __syncthreads();
        }

        // ---- per-warp epilogue: acc -> scratch -> bias -> gmem ----
        wmma::store_matrix_sync(scrF, accA, 16, wmma::mem_row_major);
        __syncwarp();
#pragma unroll
        for (int e2 = 0; e2 < 8; ++e2) {
            int e = l + e2 * 32;
            int r = e >> 4, cc = e & 15;
            int i = pm * 16 + r;
            int col = p * 96 + pn0 * 16 + cc;
            if (i < NTOK)
                out[((size_t)w * NTOK + i) * CDIM + col] = scrF[e] + par[1152 + col];
        }
        __syncwarp();
        if (wp < 8) {
            wmma::store_matrix_sync(scrF, accB, 16, wmma::mem_row_major);
            __syncwarp();
#pragma unroll
            for (int e2 = 0; e2 < 8; ++e2) {
                int e = l + e2 * 32;
                int r = e >> 4, cc = e & 15;
                int i = pm * 16 + r;
                int col = p * 96 + pn1 * 16 + cc;
                if (i < NTOK)
                    out[((size_t)w * NTOK + i) * CDIM + col] = scrF[e] + par[1152 + col];
            }
            __syncwarp();
        }
    }
}

// ---------------------------------------------------------------------------
extern "C" void kernel_launch(void* const* d_in, const int* in_sizes, int n_in,
                              void* d_out, int out_size)
{
    const float *x = 0, *mask = 0, *qkv_w = 0, *qkv_b = 0;
    const float *proj_w = 0, *proj_b = 0, *rpb = 0, *lamb = 0;

    for (int i = 0; i < n_in; ++i) {
        const float* p = (const float*)d_in[i];
        switch (in_sizes[i]) {
            case 77070336: x      = p; break;
            case 2458624:  mask   = p; break;
            case 442368:   qkv_w  = p; break;
            case 1152:     qkv_b  = p; break;
            case 147456:   proj_w = p; break;
            case 384:      proj_b = p; break;
            case 2028:     rpb    = p; break;
            case 12:       lamb   = p; break;
            default: break;
        }
    }
    if (!x || !mask || !qkv_w || !qkv_b || !proj_w || !proj_b || !rpb || !lamb) {
        x      = (const float*)d_in[0];
        mask   = (const float*)d_in[1];
        qkv_w  = (const float*)d_in[2];
        qkv_b  = (const float*)d_in[3];
        proj_w = (const float*)d_in[4];
        proj_b = (const float*)d_in[5];
        rpb    = (const float*)d_in[6];
        lamb   = (const float*)d_in[7];
    }

    prep_qkv_w<<<(NHEADS * 96 * CDIM + 255) / 256, 256>>>(qkv_w);
    prep_proj_w<<<(CDIM * CDIM + 255) / 256, 256>>>(proj_w);

    cudaFuncSetAttribute(winattn_kernel,
                         cudaFuncAttributeMaxDynamicSharedMemorySize, SMEM_BYTES);
    winattn_kernel<<<B_WIN, NT, SMEM_BYTES>>>(
        x, mask, qkv_b, proj_b, rpb, lamb, (float*)d_out);
}

// round 13
// speedup vs baseline: 1.0883x; 1.0883x over previous
#include <cuda_runtime.h>
#include <cuda_fp16.h>
#include <mma.h>
#include <cstdint>

using namespace nvcuda;

// Problem constants
#define B_WIN   4096
#define NTOK    49
#define CDIM    384
#define NHEADS  12
#define HDIM    32
#define NWIN    1024
#define SCALE_Q 0.17677669529663687f  // 32^-0.5

// Precomputed-weight globals (~1.5 MB)
__device__ __align__(256) __half g_wqkv[NHEADS * 96 * CDIM];  // head-permuted qkv_w
__device__ __align__(256) __half g_wpj_h[CDIM * CDIM];        // proj_w hi
__device__ __align__(256) __half g_wpj_l[CDIM * CDIM];        // proj_w lo

// Shared memory layout (byte offsets) — identical to R9 (2,634 µs)
#define SM_XH   0        // Xh: 64 x 392 half = 50176
#define SM_SF   50176    // GEMM staging 64x196 f32 | S 2x64x68 f32 + Sh 2x64x72 half
#define SM_WB   103424   // W staging 2 x 13824 halves = 55296 B; qkv aliases
#define SM_OH   158720   // Oh: 64 x 392 half = 50176
#define SM_MS   208896   // mask f32: 49 x 50 = 9800 (+pad)
#define SM_RB   218696   // rpb all heads fp16: 12 x 169 = 4056 (+pad)
#define SM_PAR  222752   // qkv_b(1152)+proj_b(384)+lamb(12) f32 = 6192
#define SMEM_BYTES 228944

#define XLD   392        // Xh/Oh ld (halves)
#define WLD   72         // W staging ld (halves)
#define WBUF  13824      // halves per W buffer (192*72)
#define KVLD  40         // qkv ld (halves)
#define QLD   196        // GEMM staging ld (floats)
#define SLD   68         // S f32 ld
#define SHLD  72         // Sh ld (halves)
#define PQLD  100        // proj staging ld (floats)
#define SH_OFF 34816     // byte offset of Sh inside SF region
#define PLOFF 6912       // proj lo offset within a buffer (halves)
#define NT    384

// ---------------------------------------------------------------------------
__global__ void prep_qkv_w(const float* __restrict__ qkv_w)
{
    int idx = blockIdx.x * 256 + threadIdx.x;
    if (idx < NHEADS * 96 * CDIM) {
        int h   = idx / (96 * CDIM);
        int rem = idx % (96 * CDIM);
        int j   = rem / CDIM;
        int k   = rem % CDIM;
        int g   = (j >> 5) * CDIM + h * HDIM + (j & 31);
        g_wqkv[idx] = __float2half_rn(qkv_w[(size_t)g * CDIM + k]);
    }
}

__global__ void prep_proj_w(const float* __restrict__ proj_w)
{
    int idx = blockIdx.x * 256 + threadIdx.x;
    if (idx < CDIM * CDIM) {
        float v = proj_w[idx];
        __half hi = __float2half_rn(v);
        g_wpj_h[idx] = hi;
        g_wpj_l[idx] = __float2half_rn(v - __half2float(hi));
    }
}

// ---------------------------------------------------------------------------
// Fused window attention: one block per window, 384 threads, head-pair groups,
// register-staged double-buffered GEMM (R9), warp-local epilogues.
// ---------------------------------------------------------------------------
__global__ void __launch_bounds__(NT, 1)
winattn_kernel(const float* __restrict__ x,
               const float* __restrict__ mask,
               const float* __restrict__ qkv_b,
               const float* __restrict__ proj_b,
               const float* __restrict__ rpb,
               const float* __restrict__ lamb,
               float* __restrict__ out)
{
    extern __shared__ __align__(16) char smraw[];
    __half* Xh  = (__half*)(smraw + SM_XH);
    float*  Sf  = (float*)(smraw + SM_SF);
    __half* Sh  = (__half*)(smraw + SM_SF + SH_OFF);
    __half* WB  = (__half*)(smraw + SM_WB);
    __half* qkv = WB;                               // aliases WB (phase-disjoint)
    __half* Oh  = (__half*)(smraw + SM_OH);
    float*  ms  = (float*)(smraw + SM_MS);
    __half* rb  = (__half*)(smraw + SM_RB);
    float*  par = (float*)(smraw + SM_PAR);

    const int tid = threadIdx.x;
    const int wp  = tid >> 5;
    const int l   = tid & 31;
    const int w   = blockIdx.x;

    // GEMM staging map: 192x64-half chunk = 1536 int4, 4 per thread
    int sj[4], sk[4];
#pragma unroll
    for (int i = 0; i < 4; ++i) {
        int v = tid + i * NT;
        sj[i] = v >> 3;
        sk[i] = (v & 7) << 3;
    }
    // proj staging map: hi(768 int4) + lo(768 int4), 4 per thread
    int pj[4], pk[4], psel[4];
#pragma unroll
    for (int i = 0; i < 4; ++i) {
        int v = tid + i * NT;
        psel[i] = (v >= 768);
        int v2 = v - psel[i] * 768;
        pj[i] = v2 >> 3;
        pk[i] = (v2 & 7) << 3;
    }

    // ---- init ----
    for (int t = tid; t < 49 * 96; t += NT) {
        int r = t / 96, c4 = (t % 96) * 4;
        float4 v = *(const float4*)&x[((size_t)w * NTOK + r) * CDIM + c4];
        *(__half2*)&Xh[r * XLD + c4]     = __floats2half2_rn(v.x, v.y);
        *(__half2*)&Xh[r * XLD + c4 + 2] = __floats2half2_rn(v.z, v.w);
    }
    for (int t = tid; t < 15 * 196; t += NT) {        // zero pad rows 49..63
        int r = 49 + t / 196, c2 = (t % 196) * 2;
        __half2 z = __floats2half2_rn(0.0f, 0.0f);
        *(__half2*)&Xh[r * XLD + c2] = z;
        *(__half2*)&Oh[r * XLD + c2] = z;
    }
    {
        const float* mrow = mask + (size_t)(w & (NWIN - 1)) * (NTOK * NTOK);
        for (int t = tid; t < NTOK * NTOK; t += NT)
            ms[(t / 49) * 50 + (t % 49)] = mrow[t];
    }
    for (int t = tid; t < NHEADS * 169; t += NT)
        rb[t] = __float2half_rn(rpb[(t % 169) * NHEADS + (t / 169)]);
    for (int t = tid; t < 1548; t += NT)
        par[t] = (t < 1152) ? qkv_b[t] : (t < 1536 ? proj_b[t - 1152] : lamb[t - 1536]);
    __syncthreads();

    const int mrow0 = (wp & 1) * 32;     // GEMM m-base (2 x 16-row frags)
    const int ngq   = (wp >> 1) * 32;    // QKV GEMM n-base (6 groups of 32)

    // softmax lane constants
    const int j0 = l, j1 = l + 32;
    const int j0d = j0 / 7, j0m = j0 % 7;
    const int j1d = j1 / 7, j1m = j1 % 7;

    // =============== 6 groups of 2 heads ===============
    for (int g = 0; g < 6; ++g) {
        const int h0 = 2 * g;
        const __half* Wg = g_wqkv + (size_t)h0 * (96 * CDIM);

        // ---- QKV GEMM: 64x192 = Xh @ Wg^T, Kc=64, register-staged dbl buffer ----
        wmma::fragment<wmma::accumulator, 16, 16, 16, float> acc[2][2];
#pragma unroll
        for (int i = 0; i < 2; ++i)
#pragma unroll
            for (int j = 0; j < 2; ++j) wmma::fill_fragment(acc[i][j], 0.0f);

        int4 st[4];
#pragma unroll
        for (int i = 0; i < 4; ++i)
            st[i] = *(const int4*)(Wg + (size_t)sj[i] * CDIM + sk[i]);
#pragma unroll
        for (int i = 0; i < 4; ++i)
            *(int4*)(WB + sj[i] * WLD + sk[i]) = st[i];
        __syncthreads();

        for (int c = 0; c < 6; ++c) {
            if (c < 5) {
#pragma unroll
                for (int i = 0; i < 4; ++i)
                    st[i] = *(const int4*)(Wg + (size_t)sj[i] * CDIM + (c + 1) * 64 + sk[i]);
            }
            const __half* Wc = WB + (c & 1) * WBUF;
#pragma unroll
            for (int ks = 0; ks < 4; ++ks) {
                wmma::fragment<wmma::matrix_a, 16, 16, 16, __half, wmma::row_major> a0, a1;
                wmma::load_matrix_sync(a0, &Xh[mrow0 * XLD + c * 64 + ks * 16], XLD);
                wmma::load_matrix_sync(a1, &Xh[(mrow0 + 16) * XLD + c * 64 + ks * 16], XLD);
                wmma::fragment<wmma::matrix_b, 16, 16, 16, __half, wmma::col_major> b0, b1;
                wmma::load_matrix_sync(b0, &Wc[ngq * WLD + ks * 16], WLD);
                wmma::load_matrix_sync(b1, &Wc[(ngq + 16) * WLD + ks * 16], WLD);
                wmma::mma_sync(acc[0][0], a0, b0, acc[0][0]);
                wmma::mma_sync(acc[0][1], a0, b1, acc[0][1]);
                wmma::mma_sync(acc[1][0], a1, b0, acc[1][0]);
                wmma::mma_sync(acc[1][1], a1, b1, acc[1][1]);
            }
            if (c < 5) {
#pragma unroll
                for (int i = 0; i < 4; ++i)
                    *(int4*)(WB + ((c + 1) & 1) * WBUF + sj[i] * WLD + sk[i]) = st[i];
            }
            __syncthreads();
        }

        // ---- warp-local epilogue: acc -> own Sf slice -> qkv fp16 ----
#pragma unroll
        for (int i = 0; i < 2; ++i)
#pragma unroll
            for (int j = 0; j < 2; ++j)
                wmma::store_matrix_sync(&Sf[(mrow0 + i * 16) * QLD + ngq + j * 16],
                                        acc[i][j], QLD, wmma::mem_row_major);
        __syncwarp();
        // convert own 32x32 region (rows mrow0.., cols ngq..)
#pragma unroll
        for (int k = 0; k < 32; ++k) {
            int e = l + k * 32;              // 0..1023
            int r = e >> 5, cc = e & 31;
            int row = mrow0 + r;
            if (row < NTOK) {
                int col = ngq + cc;              // 0..191
                int hh = col / 96, c2 = col % 96, which = c2 >> 5, d = c2 & 31;
                float v = Sf[row * QLD + col] + par[which * CDIM + (h0 + hh) * HDIM + d];
                if (which == 0) v *= SCALE_Q;
                qkv[hh * 7680 + which * 2560 + row * KVLD + d] = __float2half_rn(v);
            }
        }
        __syncthreads();   // qkv ready for cross-warp reads

        // ---- S = q @ k^T : 32 tiles over 12 warps; Sh pad rows zeroed here ----
        for (int t = wp; t < 32; t += 12) {
            int hh = t >> 4, mi = (t >> 2) & 3, nj = t & 3;
            const __half* qh = qkv + hh * 7680;
            const __half* kh = qh + 2560;
            wmma::fragment<wmma::accumulator, 16, 16, 16, float> sacc;
            wmma::fill_fragment(sacc, 0.0f);
#pragma unroll
            for (int ks = 0; ks < 2; ++ks) {
                wmma::fragment<wmma::matrix_a, 16, 16, 16, __half, wmma::row_major> a1;
                wmma::fragment<wmma::matrix_b, 16, 16, 16, __half, wmma::col_major> b1;
                wmma::load_matrix_sync(a1, &qh[mi * 16 * KVLD + ks * 16], KVLD);
                wmma::load_matrix_sync(b1, &kh[nj * 16 * KVLD + ks * 16], KVLD);
                wmma::mma_sync(sacc, a1, b1, sacc);
            }
            wmma::store_matrix_sync(&Sf[hh * 4352 + mi * 16 * SLD + nj * 16],
                                    sacc, SLD, wmma::mem_row_major);
        }
        // zero Sh pad rows 49..63 (both heads), cols 0..63 — 960 half2
        for (int t = tid; t < 960; t += NT) {
            int hh = t / 480, rem = t - hh * 480;
            int r = 49 + rem / 32, c2 = (rem % 32) * 2;
            *(__half2*)&Sh[hh * 4608 + r * SHLD + c2] = __floats2half2_rn(0.0f, 0.0f);
        }
        __syncthreads();

        // ---- softmax (+rpb+mask, lamb rescale) -> Sh fp16, 98 valid rows ----
        for (int t = wp; t < 98; t += 12) {
            const int hh = (t >= 49) ? 1 : 0;
            const int i  = t - hh * 49;
            __half* ShH = Sh + hh * 4608;
            const float lam1 = 1.0f + par[1536 + h0 + hh];
            const float invn = 1.0f / (float)NTOK;
            const __half* rbh = rb + (h0 + hh) * 169;
            const int i7 = i / 7, im = i - i7 * 7;
            const int r0 = (i7 - j0d + 6) * 13 + (im - j0m + 6);
            float s0 = Sf[hh * 4352 + i * SLD + j0] + __half2float(rbh[r0]) + ms[i * 50 + j0];
            float s1 = -1e30f;
            if (j1 < NTOK) {
                const int r1 = (i7 - j1d + 6) * 13 + (im - j1m + 6);
                s1 = Sf[hh * 4352 + i * SLD + j1] + __half2float(rbh[r1]) + ms[i * 50 + j1];
            }
            float mx = fmaxf(s0, s1);
#pragma unroll
            for (int off = 16; off > 0; off >>= 1)
                mx = fmaxf(mx, __shfl_xor_sync(0xffffffffu, mx, off));
            float e0 = __expf(s0 - mx);
            float e1 = (j1 < NTOK) ? __expf(s1 - mx) : 0.0f;
            float sm = e0 + e1;
#pragma unroll
            for (int off = 16; off > 0; off >>= 1)
                sm += __shfl_xor_sync(0xffffffffu, sm, off);
            const float inv = 1.0f / sm;
            ShH[i * SHLD + j0] = __float2half_rn(invn + (e0 * inv - invn) * lam1);
            ShH[i * SHLD + j1] = (j1 < NTOK)
                ? __float2half_rn(invn + (e1 * inv - invn) * lam1)
                : __float2half_rn(0.0f);
        }
        __syncthreads();

        // ---- O = attn @ v : 16 tiles over 12 warps, warp-local convert ----
        for (int t = wp; t < 16; t += 12) {
            int hh = t >> 3, mi = (t >> 1) & 3, nj = t & 1;
            const __half* ShH = Sh + hh * 4608;
            const __half* vhh = qkv + hh * 7680 + 5120;
            wmma::fragment<wmma::accumulator, 16, 16, 16, float> oacc;
            wmma::fill_fragment(oacc, 0.0f);
#pragma unroll
            for (int ks = 0; ks < 4; ++ks) {
                wmma::fragment<wmma::matrix_a, 16, 16, 16, __half, wmma::row_major> a1;
                wmma::fragment<wmma::matrix_b, 16, 16, 16, __half, wmma::row_major> b1;
                wmma::load_matrix_sync(a1, &ShH[mi * 16 * SHLD + ks * 16], SHLD);
                wmma::load_matrix_sync(b1, &vhh[ks * 16 * KVLD + nj * 16], KVLD);
                wmma::mma_sync(oacc, a1, b1, oacc);
            }
            float* dstF = &Sf[hh * 4352 + mi * 16 * SLD + nj * 16];
            wmma::store_matrix_sync(dstF, oacc, SLD, wmma::mem_row_major);
            __syncwarp();
            // convert own 16x16 tile -> Oh
#pragma unroll
            for (int k = 0; k < 8; ++k) {
                int e = l + k * 32;
                int r = e >> 4, cc = e & 15;
                int i = mi * 16 + r;
                if (i < NTOK)
                    Oh[i * XLD + (h0 + hh) * HDIM + nj * 16 + cc] =
                        __float2half_rn(dstF[r * SLD + cc]);
            }
        }
        __syncthreads();   // Oh written; qkv (WB) free for next group staging
    }

    // =============== proj: out = Oh @ proj_w^T + b (hi/lo staged) ===============
    const int np6 = (wp >> 1);      // n-tile 0..5 (16 cols each)

    int4 pst[4];
#pragma unroll
    for (int i = 0; i < 4; ++i)
        pst[i] = *(const int4*)((psel[i] ? g_wpj_l : g_wpj_h)
                                + (size_t)pj[i] * CDIM + pk[i]);
#pragma unroll
    for (int i = 0; i < 4; ++i)
        *(int4*)(WB + psel[i] * PLOFF + pj[i] * WLD + pk[i]) = pst[i];
    __syncthreads();

    for (int p = 0; p < 4; ++p) {
        wmma::fragment<wmma::accumulator, 16, 16, 16, float> acc2[2];
        wmma::fill_fragment(acc2[0], 0.0f);
        wmma::fill_fragment(acc2[1], 0.0f);

        for (int c = 0; c < 6; ++c) {
            const bool more = (c < 5) || (p < 3);
            if (more) {
                const int np_ = (c < 5) ? p : p + 1;
                const int nc_ = (c < 5) ? c + 1 : 0;
#pragma unroll
                for (int i = 0; i < 4; ++i)
                    pst[i] = *(const int4*)((psel[i] ? g_wpj_l : g_wpj_h)
                             + (size_t)(np_ * 96 + pj[i]) * CDIM + nc_ * 64 + pk[i]);
            }
            const __half* Wc = WB + (c & 1) * WBUF;
#pragma unroll
            for (int ks = 0; ks < 4; ++ks) {
                wmma::fragment<wmma::matrix_a, 16, 16, 16, __half, wmma::row_major> a0, a1;
                wmma::load_matrix_sync(a0, &Oh[mrow0 * XLD + c * 64 + ks * 16], XLD);
                wmma::load_matrix_sync(a1, &Oh[(mrow0 + 16) * XLD + c * 64 + ks * 16], XLD);
                wmma::fragment<wmma::matrix_b, 16, 16, 16, __half, wmma::col_major> bh, bl;
                wmma::load_matrix_sync(bh, &Wc[np6 * 16 * WLD + ks * 16], WLD);
                wmma::load_matrix_sync(bl, &Wc[PLOFF + np6 * 16 * WLD + ks * 16], WLD);
                wmma::mma_sync(acc2[0], a0, bh, acc2[0]);
                wmma::mma_sync(acc2[0], a0, bl, acc2[0]);
                wmma::mma_sync(acc2[1], a1, bh, acc2[1]);
                wmma::mma_sync(acc2[1], a1, bl, acc2[1]);
            }
            if (more) {
#pragma unroll
                for (int i = 0; i < 4; ++i)
                    *(int4*)(WB + ((c + 1) & 1) * WBUF
                             + psel[i] * PLOFF + pj[i] * WLD + pk[i]) = pst[i];
            }
            __syncthreads();
        }

        // ---- warp-local epilogue: own 2 tiles -> bias -> gmem (no barriers) ----
#pragma unroll
        for (int i = 0; i < 2; ++i) {
            float* dstF = &Sf[(mrow0 + i * 16) * PQLD + np6 * 16];
            wmma::store_matrix_sync(dstF, acc2[i], PQLD, wmma::mem_row_major);
            __syncwarp();
#pragma unroll
            for (int k = 0; k < 8; ++k) {
                int e = l + k * 32;
                int r = e >> 4, cc = e & 15;
                int row = mrow0 + i * 16 + r;
                int col = p * 96 + np6 * 16 + cc;
                if (row < NTOK)
                    out[((size_t)w * NTOK + row) * CDIM + col] =
                        dstF[r * PQLD + cc] + par[1152 + col];
            }
            __syncwarp();
        }
    }
}

// ---------------------------------------------------------------------------
extern "C" void kernel_launch(void* const* d_in, const int* in_sizes, int n_in,
                              void* d_out, int out_size)
{
    const float *x = 0, *mask = 0, *qkv_w = 0, *qkv_b = 0;
    const float *proj_w = 0, *proj_b = 0, *rpb = 0, *lamb = 0;

    for (int i = 0; i < n_in; ++i) {
        const float* p = (const float*)d_in[i];
        switch (in_sizes[i]) {
            case 77070336: x      = p; break;
            case 2458624:  mask   = p; break;
            case 442368:   qkv_w  = p; break;
            case 1152:     qkv_b  = p; break;
            case 147456:   proj_w = p; break;
            case 384:      proj_b = p; break;
            case 2028:     rpb    = p; break;
            case 12:       lamb   = p; break;
            default: break;
        }
    }
    if (!x || !mask || !qkv_w || !qkv_b || !proj_w || !proj_b || !rpb || !lamb) {
        x      = (const float*)d_in[0];
        mask   = (const float*)d_in[1];
        qkv_w  = (const float*)d_in[2];
        qkv_b  = (const float*)d_in[3];
        proj_w = (const float*)d_in[4];
        proj_b = (const float*)d_in[5];
        rpb    = (const float*)d_in[6];
        lamb   = (const float*)d_in[7];
    }

    prep_qkv_w<<<(NHEADS * 96 * CDIM + 255) / 256, 256>>>(qkv_w);
    prep_proj_w<<<(CDIM * CDIM + 255) / 256, 256>>>(proj_w);

    cudaFuncSetAttribute(winattn_kernel,
                         cudaFuncAttributeMaxDynamicSharedMemorySize, SMEM_BYTES);
    winattn_kernel<<<B_WIN, NT, SMEM_BYTES>>>(
        x, mask, qkv_b, proj_b, rpb, lamb, (float*)d_out);
}

// round 15
// speedup vs baseline: 1.1921x; 1.0954x over previous
#include <cuda_runtime.h>
#include <cuda_fp16.h>
#include <mma.h>
#include <cstdint>

using namespace nvcuda;

// Problem constants
#define B_WIN   4096
#define NTOK    49
#define CDIM    384
#define NHEADS  12
#define HDIM    32
#define NWIN    1024
#define SCALE_Q 0.17677669529663687f  // 32^-0.5

// Precomputed-weight globals (~1.2 MB)
__device__ __align__(256) __half g_wqkv[NHEADS * 96 * CDIM];  // head-permuted qkv_w
__device__ __align__(256) __half g_wpj[CDIM * CDIM];          // proj_w fp16

// Shared memory layout (byte offsets) — identical to R9 (2,634 µs)
#define SM_XH   0        // Xh: 64 x 392 half = 50176
#define SM_SF   50176    // GEMM staging 64x196 f32 | S 2x64x68 f32 + Sh 2x64x72 half
#define SM_WB   103424   // W staging 2 x 13824 halves = 55296 B; qkv aliases
#define SM_OH   158720   // Oh: 64 x 392 half = 50176
#define SM_MS   208896   // mask f32: 49 x 50 = 9800 (+pad)
#define SM_RB   218696   // rpb all heads fp16: 12 x 169 = 4056 (+pad)
#define SM_PAR  222752   // qkv_b(1152)+proj_b(384)+lamb(12) f32 = 6192
#define SMEM_BYTES 228944

#define XLD   392        // Xh/Oh ld (halves)
#define WLD   72         // qkv W staging ld (halves)
#define WBUF  13824      // halves per W buffer
#define KVLD  40         // qkv ld (halves)
#define QLD   196        // GEMM staging ld (floats)
#define SLD   68         // S f32 ld
#define SHLD  72         // Sh ld (halves)
#define PQLD  100        // proj staging ld (floats)
#define SH_OFF 34816     // byte offset of Sh inside SF region
#define WLD2  136        // proj W staging ld (halves), Kc=128 (+8 pad)
#define NT    384

// ---------------------------------------------------------------------------
__global__ void prep_qkv_w(const float* __restrict__ qkv_w)
{
    int idx = blockIdx.x * 256 + threadIdx.x;
    if (idx < NHEADS * 96 * CDIM) {
        int h   = idx / (96 * CDIM);
        int rem = idx % (96 * CDIM);
        int j   = rem / CDIM;
        int k   = rem % CDIM;
        int g   = (j >> 5) * CDIM + h * HDIM + (j & 31);
        g_wqkv[idx] = __float2half_rn(qkv_w[(size_t)g * CDIM + k]);
    }
}

__global__ void prep_proj_w(const float* __restrict__ proj_w)
{
    int idx = blockIdx.x * 256 + threadIdx.x;
    if (idx < CDIM * CDIM)
        g_wpj[idx] = __float2half_rn(proj_w[idx]);
}

// ---------------------------------------------------------------------------
// Fused window attention: one block per window, 384 threads, head-pair groups,
// register-staged double-buffered GEMM (R9 base); proj single-fp16, Kc=128,
// global chunk-parity across the proj loop.
// ---------------------------------------------------------------------------
__global__ void __launch_bounds__(NT, 1)
winattn_kernel(const float* __restrict__ x,
               const float* __restrict__ mask,
               const float* __restrict__ qkv_b,
               const float* __restrict__ proj_b,
               const float* __restrict__ rpb,
               const float* __restrict__ lamb,
               float* __restrict__ out)
{
    extern __shared__ __align__(16) char smraw[];
    __half* Xh  = (__half*)(smraw + SM_XH);
    float*  Sf  = (float*)(smraw + SM_SF);
    __half* Sh  = (__half*)(smraw + SM_SF + SH_OFF);
    __half* WB  = (__half*)(smraw + SM_WB);
    __half* qkv = WB;                               // aliases WB (phase-disjoint)
    __half* Oh  = (__half*)(smraw + SM_OH);
    float*  ms  = (float*)(smraw + SM_MS);
    __half* rb  = (__half*)(smraw + SM_RB);
    float*  par = (float*)(smraw + SM_PAR);

    const int tid = threadIdx.x;
    const int wp  = tid >> 5;
    const int l   = tid & 31;
    const int w   = blockIdx.x;

    // qkv GEMM staging map: 192x64-half chunk = 1536 int4, 4 per thread
    int sj[4], sk[4];
#pragma unroll
    for (int i = 0; i < 4; ++i) {
        int v = tid + i * NT;
        sj[i] = v >> 3;
        sk[i] = (v & 7) << 3;
    }
    // proj staging map: 96x128-half chunk = 1536 int4, 4 per thread
    int pj[4], pk[4];
#pragma unroll
    for (int i = 0; i < 4; ++i) {
        int v = tid + i * NT;
        pj[i] = v >> 4;
        pk[i] = (v & 15) << 3;
    }

    // ---- init ----
    for (int t = tid; t < 49 * 96; t += NT) {
        int r = t / 96, c4 = (t % 96) * 4;
        float4 v = *(const float4*)&x[((size_t)w * NTOK + r) * CDIM + c4];
        *(__half2*)&Xh[r * XLD + c4]     = __floats2half2_rn(v.x, v.y);
        *(__half2*)&Xh[r * XLD + c4 + 2] = __floats2half2_rn(v.z, v.w);
    }
    for (int t = tid; t < 15 * 196; t += NT) {        // zero pad rows 49..63
        int r = 49 + t / 196, c2 = (t % 196) * 2;
        __half2 z = __floats2half2_rn(0.0f, 0.0f);
        *(__half2*)&Xh[r * XLD + c2] = z;
        *(__half2*)&Oh[r * XLD + c2] = z;
    }
    {
        const float* mrow = mask + (size_t)(w & (NWIN - 1)) * (NTOK * NTOK);
        for (int t = tid; t < NTOK * NTOK; t += NT)
            ms[(t / 49) * 50 + (t % 49)] = mrow[t];
    }
    for (int t = tid; t < NHEADS * 169; t += NT)
        rb[t] = __float2half_rn(rpb[(t % 169) * NHEADS + (t / 169)]);
    for (int t = tid; t < 1548; t += NT)
        par[t] = (t < 1152) ? qkv_b[t] : (t < 1536 ? proj_b[t - 1152] : lamb[t - 1536]);
    __syncthreads();

    const int mrow0 = (wp & 1) * 32;     // GEMM m-base (2 x 16-row frags)
    const int ngq   = (wp >> 1) * 32;    // QKV GEMM n-base (6 groups of 32)

    // =============== 6 groups of 2 heads ===============
    for (int g = 0; g < 6; ++g) {
        const int h0 = 2 * g;
        const __half* Wg = g_wqkv + (size_t)h0 * (96 * CDIM);

        // ---- QKV GEMM: 64x192 = Xh @ Wg^T, Kc=64, register-staged dbl buffer ----
        wmma::fragment<wmma::accumulator, 16, 16, 16, float> acc[2][2];
#pragma unroll
        for (int i = 0; i < 2; ++i)
#pragma unroll
            for (int j = 0; j < 2; ++j) wmma::fill_fragment(acc[i][j], 0.0f);

        int4 st[4];
#pragma unroll
        for (int i = 0; i < 4; ++i)
            st[i] = *(const int4*)(Wg + (size_t)sj[i] * CDIM + sk[i]);
#pragma unroll
        for (int i = 0; i < 4; ++i)
            *(int4*)(WB + sj[i] * WLD + sk[i]) = st[i];
        __syncthreads();

        for (int c = 0; c < 6; ++c) {
            if (c < 5) {
#pragma unroll
                for (int i = 0; i < 4; ++i)
                    st[i] = *(const int4*)(Wg + (size_t)sj[i] * CDIM + (c + 1) * 64 + sk[i]);
            }
            const __half* Wc = WB + (c & 1) * WBUF;
#pragma unroll
            for (int ks = 0; ks < 4; ++ks) {
                wmma::fragment<wmma::matrix_a, 16, 16, 16, __half, wmma::row_major> a0, a1;
                wmma::load_matrix_sync(a0, &Xh[mrow0 * XLD + c * 64 + ks * 16], XLD);
                wmma::load_matrix_sync(a1, &Xh[(mrow0 + 16) * XLD + c * 64 + ks * 16], XLD);
                wmma::fragment<wmma::matrix_b, 16, 16, 16, __half, wmma::col_major> b0, b1;
                wmma::load_matrix_sync(b0, &Wc[ngq * WLD + ks * 16], WLD);
                wmma::load_matrix_sync(b1, &Wc[(ngq + 16) * WLD + ks * 16], WLD);
                wmma::mma_sync(acc[0][0], a0, b0, acc[0][0]);
                wmma::mma_sync(acc[0][1], a0, b1, acc[0][1]);
                wmma::mma_sync(acc[1][0], a1, b0, acc[1][0]);
                wmma::mma_sync(acc[1][1], a1, b1, acc[1][1]);
            }
            if (c < 5) {
#pragma unroll
                for (int i = 0; i < 4; ++i)
                    *(int4*)(WB + ((c + 1) & 1) * WBUF + sj[i] * WLD + sk[i]) = st[i];
            }
            __syncthreads();
        }
#pragma unroll
        for (int i = 0; i < 2; ++i)
#pragma unroll
            for (int j = 0; j < 2; ++j)
                wmma::store_matrix_sync(&Sf[(mrow0 + i * 16) * QLD + ngq + j * 16],
                                        acc[i][j], QLD, wmma::mem_row_major);
        __syncthreads();

        // ---- bias + q-scale + convert -> qkv fp16 ----
        for (int t = tid; t < 49 * 192; t += NT) {
            int r = t / 192, cc = t % 192;
            int hh = cc / 96, c2 = cc % 96, which = c2 >> 5, d = c2 & 31;
            float vv = Sf[r * QLD + cc] + par[which * CDIM + (h0 + hh) * HDIM + d];
            if (which == 0) vv *= SCALE_Q;
            qkv[hh * 7680 + which * 2560 + r * KVLD + d] = __float2half_rn(vv);
        }
        __syncthreads();

        // ---- S = q @ k^T : 32 tiles over 12 warps ----
        for (int t = wp; t < 32; t += 12) {
            int hh = t >> 4, mi = (t >> 2) & 3, nj = t & 3;
            const __half* qh = qkv + hh * 7680;
            const __half* kh = qh + 2560;
            wmma::fragment<wmma::accumulator, 16, 16, 16, float> sacc;
            wmma::fill_fragment(sacc, 0.0f);
#pragma unroll
            for (int ks = 0; ks < 2; ++ks) {
                wmma::fragment<wmma::matrix_a, 16, 16, 16, __half, wmma::row_major> a1;
                wmma::fragment<wmma::matrix_b, 16, 16, 16, __half, wmma::col_major> b1;
                wmma::load_matrix_sync(a1, &qh[mi * 16 * KVLD + ks * 16], KVLD);
                wmma::load_matrix_sync(b1, &kh[nj * 16 * KVLD + ks * 16], KVLD);
                wmma::mma_sync(sacc, a1, b1, sacc);
            }
            wmma::store_matrix_sync(&Sf[hh * 4352 + mi * 16 * SLD + nj * 16],
                                    sacc, SLD, wmma::mem_row_major);
        }
        __syncthreads();

        // ---- softmax (+rpb+mask, lamb rescale) -> Sh fp16; zero pads ----
        for (int i2 = wp; i2 < 128; i2 += 12) {
            int hh = i2 >> 6, i = i2 & 63;
            __half* ShH = Sh + hh * 4608;
            if (i < NTOK) {
                const float lam1 = 1.0f + par[1536 + h0 + hh];
                const float invn = 1.0f / (float)NTOK;
                const __half* rbh = rb + (h0 + hh) * 169;
                const int i7 = i / 7, im = i - i7 * 7;
                const int j0 = l, j1 = l + 32;
                const int r0 = (i7 - j0 / 7 + 6) * 13 + (im - j0 % 7 + 6);
                float s0 = Sf[hh * 4352 + i * SLD + j0] + __half2float(rbh[r0]) + ms[i * 50 + j0];
                float s1 = -1e30f;
                if (j1 < NTOK) {
                    const int r1 = (i7 - j1 / 7 + 6) * 13 + (im - j1 % 7 + 6);
                    s1 = Sf[hh * 4352 + i * SLD + j1] + __half2float(rbh[r1]) + ms[i * 50 + j1];
                }
                float mx = fmaxf(s0, s1);
#pragma unroll
                for (int off = 16; off > 0; off >>= 1)
                    mx = fmaxf(mx, __shfl_xor_sync(0xffffffffu, mx, off));
                float e0 = __expf(s0 - mx);
                float e1 = (j1 < NTOK) ? __expf(s1 - mx) : 0.0f;
                float sm = e0 + e1;
#pragma unroll
                for (int off = 16; off > 0; off >>= 1)
                    sm += __shfl_xor_sync(0xffffffffu, sm, off);
                const float inv = 1.0f / sm;
                ShH[i * SHLD + j0] = __float2half_rn(invn + (e0 * inv - invn) * lam1);
                ShH[i * SHLD + j1] = (j1 < NTOK)
                    ? __float2half_rn(invn + (e1 * inv - invn) * lam1)
                    : __float2half_rn(0.0f);
            } else {
                ShH[i * SHLD + l]      = __float2half_rn(0.0f);
                ShH[i * SHLD + l + 32] = __float2half_rn(0.0f);
            }
        }
        __syncthreads();

        // ---- O = attn @ v : 16 tiles over 12 warps ----
        for (int t = wp; t < 16; t += 12) {
            int hh = t >> 3, mi = (t >> 1) & 3, nj = t & 1;
            const __half* ShH = Sh + hh * 4608;
            const __half* vhh = qkv + hh * 7680 + 5120;
            wmma::fragment<wmma::accumulator, 16, 16, 16, float> oacc;
            wmma::fill_fragment(oacc, 0.0f);
#pragma unroll
            for (int ks = 0; ks < 4; ++ks) {
                wmma::fragment<wmma::matrix_a, 16, 16, 16, __half, wmma::row_major> a1;
                wmma::fragment<wmma::matrix_b, 16, 16, 16, __half, wmma::row_major> b1;
                wmma::load_matrix_sync(a1, &ShH[mi * 16 * SHLD + ks * 16], SHLD);
                wmma::load_matrix_sync(b1, &vhh[ks * 16 * KVLD + nj * 16], KVLD);
                wmma::mma_sync(oacc, a1, b1, oacc);
            }
            wmma::store_matrix_sync(&Sf[hh * 4352 + mi * 16 * SLD + nj * 16],
                                    oacc, SLD, wmma::mem_row_major);
        }
        __syncthreads();

        // ---- convert O -> Oh ----
        for (int t = tid; t < 49 * 64; t += NT) {
            int r = t >> 6, cc = t & 63, hh = cc >> 5, d = cc & 31;
            Oh[r * XLD + (h0 + hh) * HDIM + d] = __float2half_rn(Sf[hh * 4352 + r * SLD + d]);
        }
        __syncthreads();
    }

    // =============== proj: out = Oh @ proj_w^T + b (single fp16, Kc=128) ===============
    const int np6 = (wp >> 1);      // n-tile 0..5 (16 cols each)

    int4 pst[4];
#pragma unroll
    for (int i = 0; i < 4; ++i)
        pst[i] = *(const int4*)(g_wpj + (size_t)pj[i] * CDIM + pk[i]);
#pragma unroll
    for (int i = 0; i < 4; ++i)
        *(int4*)(WB + pj[i] * WLD2 + pk[i]) = pst[i];
    __syncthreads();

    int cb = 0;   // global chunk parity: current chunk resides in buf (cb & 1)
    for (int p = 0; p < 4; ++p) {
        wmma::fragment<wmma::accumulator, 16, 16, 16, float> acc2[2];
        wmma::fill_fragment(acc2[0], 0.0f);
        wmma::fill_fragment(acc2[1], 0.0f);

        for (int c = 0; c < 3; ++c, ++cb) {
            const bool more = (c < 2) || (p < 3);
            if (more) {
                const int np_ = (c < 2) ? p : p + 1;
                const int nc_ = (c < 2) ? c + 1 : 0;
#pragma unroll
                for (int i = 0; i < 4; ++i)
                    pst[i] = *(const int4*)(g_wpj
                             + (size_t)(np_ * 96 + pj[i]) * CDIM + nc_ * 128 + pk[i]);
            }
            const __half* Wc = WB + (cb & 1) * WBUF;
#pragma unroll
            for (int ks = 0; ks < 8; ++ks) {
                wmma::fragment<wmma::matrix_a, 16, 16, 16, __half, wmma::row_major> a0, a1;
                wmma::load_matrix_sync(a0, &Oh[mrow0 * XLD + c * 128 + ks * 16], XLD);
                wmma::load_matrix_sync(a1, &Oh[(mrow0 + 16) * XLD + c * 128 + ks * 16], XLD);
                wmma::fragment<wmma::matrix_b, 16, 16, 16, __half, wmma::col_major> b1;
                wmma::load_matrix_sync(b1, &Wc[np6 * 16 * WLD2 + ks * 16], WLD2);
                wmma::mma_sync(acc2[0], a0, b1, acc2[0]);
                wmma::mma_sync(acc2[1], a1, b1, acc2[1]);
            }
            if (more) {
#pragma unroll
                for (int i = 0; i < 4; ++i)
                    *(int4*)(WB + ((cb + 1) & 1) * WBUF + pj[i] * WLD2 + pk[i]) = pst[i];
            }
            __syncthreads();
        }

        wmma::store_matrix_sync(&Sf[mrow0 * PQLD + np6 * 16], acc2[0], PQLD, wmma::mem_row_major);
        wmma::store_matrix_sync(&Sf[(mrow0 + 16) * PQLD + np6 * 16], acc2[1], PQLD, wmma::mem_row_major);
        __syncthreads();

        for (int t = tid; t < 49 * 96; t += NT) {
            int r = t / 96, cc = t % 96;
            out[((size_t)w * NTOK + r) * CDIM + p * 96 + cc] = Sf[r * PQLD + cc] + par[1152 + p * 96 + cc];
        }
        __syncthreads();
    }
}

// ---------------------------------------------------------------------------
extern "C" void kernel_launch(void* const* d_in, const int* in_sizes, int n_in,
                              void* d_out, int out_size)
{
    const float *x = 0, *mask = 0, *qkv_w = 0, *qkv_b = 0;
    const float *proj_w = 0, *proj_b = 0, *rpb = 0, *lamb = 0;

    for (int i = 0; i < n_in; ++i) {
        const float* p = (const float*)d_in[i];
        switch (in_sizes[i]) {
            case 77070336: x      = p; break;
            case 2458624:  mask   = p; break;
            case 442368:   qkv_w  = p; break;
            case 1152:     qkv_b  = p; break;
            case 147456:   proj_w = p; break;
            case 384:      proj_b = p; break;
            case 2028:     rpb    = p; break;
            case 12:       lamb   = p; break;
            default: break;
        }
    }
    if (!x || !mask || !qkv_w || !qkv_b || !proj_w || !proj_b || !rpb || !lamb) {
        x      = (const float*)d_in[0];
        mask   = (const float*)d_in[1];
        qkv_w  = (const float*)d_in[2];
        qkv_b  = (const float*)d_in[3];
        proj_w = (const float*)d_in[4];
        proj_b = (const float*)d_in[5];
        rpb    = (const float*)d_in[6];
        lamb   = (const float*)d_in[7];
    }

    prep_qkv_w<<<(NHEADS * 96 * CDIM + 255) / 256, 256>>>(qkv_w);
    prep_proj_w<<<(CDIM * CDIM + 255) / 256, 256>>>(proj_w);

    cudaFuncSetAttribute(winattn_kernel,
                         cudaFuncAttributeMaxDynamicSharedMemorySize, SMEM_BYTES);
    winattn_kernel<<<B_WIN, NT, SMEM_BYTES>>>(
        x, mask, qkv_b, proj_b, rpb, lamb, (float*)d_out);
}